// round 2
// baseline (speedup 1.0000x reference)
#include <cuda_runtime.h>
#include <cuda_bf16.h>

#define NEDGES 65536
#define DNODE  1024
#define DHID   1024

// 256 MB scratch for the hidden activation H = relu([Xs|Xd] @ W1 + b1)
__device__ float g_H[(size_t)NEDGES * DHID];

// ---------------------------------------------------------------------------
// Stage 1: H[e, :] = relu( concat(nf[src[e]], nf[dst[e]]) @ W1 + b1 )
//   M = NEDGES, K = 2*DNODE, N = DHID.  A is gathered on the fly.
// ---------------------------------------------------------------------------
__global__ __launch_bounds__(256, 2)
void stage1_kernel(const float* __restrict__ nf,
                   const int* __restrict__ src,
                   const int* __restrict__ dst,
                   const float* __restrict__ W1,   // [2*DNODE, DHID] row-major
                   const float* __restrict__ b1)
{
    const int BM = 128, BN = 128, BK = 8;
    const int K = 2 * DNODE;
    const int N = DHID;

    __shared__ float As[BK][BM];
    __shared__ float Bs[BK][BN];

    const int tid = threadIdx.x;
    const int m0  = blockIdx.y * BM;
    const int n0  = blockIdx.x * BN;

    // A-load role: one float4 along K per thread
    const int arow = tid >> 1;          // 0..127 (edge within tile)
    const int akk  = (tid & 1) * 4;     // 0 or 4
    // B-load role: one float4 along N per thread
    const int brow = tid >> 5;          // 0..7
    const int bcol = (tid & 31) * 4;    // 0..124

    const int sIdx = src[m0 + arow];
    const int dIdx = dst[m0 + arow];
    const float* srcRow = nf + (size_t)sIdx * DNODE;
    const float* dstRow = nf + (size_t)dIdx * DNODE;

    const int tm = (tid >> 4) * 8;
    const int tn = (tid & 15) * 8;

    float acc[8][8];
    #pragma unroll
    for (int i = 0; i < 8; ++i)
        #pragma unroll
        for (int j = 0; j < 8; ++j) acc[i][j] = 0.0f;

    for (int kb = 0; kb < K; kb += BK) {
        // global -> regs
        const float* abase = (kb < DNODE) ? (srcRow + kb) : (dstRow + (kb - DNODE));
        float4 av = *reinterpret_cast<const float4*>(abase + akk);
        float4 bv = *reinterpret_cast<const float4*>(W1 + (size_t)(kb + brow) * N + n0 + bcol);

        __syncthreads();   // protect previous tile reads
        As[akk + 0][arow] = av.x;
        As[akk + 1][arow] = av.y;
        As[akk + 2][arow] = av.z;
        As[akk + 3][arow] = av.w;
        *reinterpret_cast<float4*>(&Bs[brow][bcol]) = bv;
        __syncthreads();

        #pragma unroll
        for (int k = 0; k < BK; ++k) {
            float4 a0 = *reinterpret_cast<const float4*>(&As[k][tm]);
            float4 a1 = *reinterpret_cast<const float4*>(&As[k][tm + 4]);
            float4 bb0 = *reinterpret_cast<const float4*>(&Bs[k][tn]);
            float4 bb1 = *reinterpret_cast<const float4*>(&Bs[k][tn + 4]);
            float a[8] = {a0.x, a0.y, a0.z, a0.w, a1.x, a1.y, a1.z, a1.w};
            float b[8] = {bb0.x, bb0.y, bb0.z, bb0.w, bb1.x, bb1.y, bb1.z, bb1.w};
            #pragma unroll
            for (int i = 0; i < 8; ++i)
                #pragma unroll
                for (int j = 0; j < 8; ++j)
                    acc[i][j] = fmaf(a[i], b[j], acc[i][j]);
        }
    }

    // epilogue: bias + relu -> g_H
    float bb[8];
    #pragma unroll
    for (int j = 0; j < 8; ++j) bb[j] = b1[n0 + tn + j];

    #pragma unroll
    for (int i = 0; i < 8; ++i) {
        size_t row = (size_t)(m0 + tm + i);
        float v[8];
        #pragma unroll
        for (int j = 0; j < 8; ++j) {
            float x = acc[i][j] + bb[j];
            v[j] = x > 0.0f ? x : 0.0f;
        }
        float4* out0 = reinterpret_cast<float4*>(&g_H[row * DHID + n0 + tn]);
        out0[0] = make_float4(v[0], v[1], v[2], v[3]);
        out0[1] = make_float4(v[4], v[5], v[6], v[7]);
    }
}

// ---------------------------------------------------------------------------
// Stage 2: OUT = H @ W2 + b2
//   M = NEDGES, K = DHID, N = DHID
// ---------------------------------------------------------------------------
__global__ __launch_bounds__(256, 2)
void stage2_kernel(const float* __restrict__ W2,   // [DHID, DHID] row-major
                   const float* __restrict__ b2,
                   float* __restrict__ out)
{
    const int BM = 128, BN = 128, BK = 8;
    const int K = DHID;
    const int N = DHID;

    __shared__ float As[BK][BM];
    __shared__ float Bs[BK][BN];

    const int tid = threadIdx.x;
    const int m0  = blockIdx.y * BM;
    const int n0  = blockIdx.x * BN;

    const int arow = tid >> 1;
    const int akk  = (tid & 1) * 4;
    const int brow = tid >> 5;
    const int bcol = (tid & 31) * 4;

    const float* rowA = g_H + (size_t)(m0 + arow) * K;

    const int tm = (tid >> 4) * 8;
    const int tn = (tid & 15) * 8;

    float acc[8][8];
    #pragma unroll
    for (int i = 0; i < 8; ++i)
        #pragma unroll
        for (int j = 0; j < 8; ++j) acc[i][j] = 0.0f;

    for (int kb = 0; kb < K; kb += BK) {
        float4 av = *reinterpret_cast<const float4*>(rowA + kb + akk);
        float4 bv = *reinterpret_cast<const float4*>(W2 + (size_t)(kb + brow) * N + n0 + bcol);

        __syncthreads();
        As[akk + 0][arow] = av.x;
        As[akk + 1][arow] = av.y;
        As[akk + 2][arow] = av.z;
        As[akk + 3][arow] = av.w;
        *reinterpret_cast<float4*>(&Bs[brow][bcol]) = bv;
        __syncthreads();

        #pragma unroll
        for (int k = 0; k < BK; ++k) {
            float4 a0 = *reinterpret_cast<const float4*>(&As[k][tm]);
            float4 a1 = *reinterpret_cast<const float4*>(&As[k][tm + 4]);
            float4 bb0 = *reinterpret_cast<const float4*>(&Bs[k][tn]);
            float4 bb1 = *reinterpret_cast<const float4*>(&Bs[k][tn + 4]);
            float a[8] = {a0.x, a0.y, a0.z, a0.w, a1.x, a1.y, a1.z, a1.w};
            float b[8] = {bb0.x, bb0.y, bb0.z, bb0.w, bb1.x, bb1.y, bb1.z, bb1.w};
            #pragma unroll
            for (int i = 0; i < 8; ++i)
                #pragma unroll
                for (int j = 0; j < 8; ++j)
                    acc[i][j] = fmaf(a[i], b[j], acc[i][j]);
        }
    }

    float bb[8];
    #pragma unroll
    for (int j = 0; j < 8; ++j) bb[j] = b2[n0 + tn + j];

    #pragma unroll
    for (int i = 0; i < 8; ++i) {
        size_t row = (size_t)(m0 + tm + i);
        float v[8];
        #pragma unroll
        for (int j = 0; j < 8; ++j) v[j] = acc[i][j] + bb[j];
        float4* out0 = reinterpret_cast<float4*>(&out[row * (size_t)DHID + n0 + tn]);
        out0[0] = make_float4(v[0], v[1], v[2], v[3]);
        out0[1] = make_float4(v[4], v[5], v[6], v[7]);
    }
}

extern "C" void kernel_launch(void* const* d_in, const int* in_sizes, int n_in,
                              void* d_out, int out_size)
{
    const float* nf  = (const float*)d_in[0];
    const int*   src = (const int*)d_in[1];   // JAX int64 silently downcasts to int32 (x64 disabled)
    const int*   dst = (const int*)d_in[2];
    const float* W1  = (const float*)d_in[3];
    const float* b1  = (const float*)d_in[4];
    const float* W2  = (const float*)d_in[5];
    const float* b2  = (const float*)d_in[6];
    float*       out = (float*)d_out;

    dim3 grid(DHID / 128, NEDGES / 128);
    stage1_kernel<<<grid, 256>>>(nf, src, dst, W1, b1);
    stage2_kernel<<<grid, 256>>>(W2, b2, out);
}

// round 7
// speedup vs baseline: 1.7228x; 1.7228x over previous
#include <cuda_runtime.h>
#include <cuda_bf16.h>
#include <mma.h>
#include <cstdint>

using namespace nvcuda;

#define NEDGES 65536
#define NNODES 50000
#define DNODE  1024
#define DHID   1024

// ---------------------------------------------------------------------------
// Device scratch (static). IMPORTANT: referenced ONLY from device code —
// passing a __device__ array as a kernel argument from host passes the host
// shadow address (and on GB300/ATS it silently writes host memory!).
// ---------------------------------------------------------------------------
__device__ __nv_bfloat16 g_nf_hi[(size_t)NNODES * DNODE];
__device__ __nv_bfloat16 g_nf_lo[(size_t)NNODES * DNODE];
__device__ __nv_bfloat16 g_W1T_hi[(size_t)DHID * (2 * DNODE)];   // [N=1024][K=2048]
__device__ __nv_bfloat16 g_W1T_lo[(size_t)DHID * (2 * DNODE)];
__device__ __nv_bfloat16 g_W2T_hi[(size_t)DHID * DHID];          // [N=1024][K=1024]
__device__ __nv_bfloat16 g_W2T_lo[(size_t)DHID * DHID];
__device__ __nv_bfloat16 g_H_hi[(size_t)NEDGES * DHID];
__device__ __nv_bfloat16 g_H_lo[(size_t)NEDGES * DHID];

__device__ __forceinline__ void split1(float x, __nv_bfloat16& h, __nv_bfloat16& l) {
    h = __float2bfloat16(x);
    l = __float2bfloat16(x - __bfloat162float(h));
}

// ---------------------------------------------------------------------------
// Pre-pass: fp32 -> bf16 hi/lo split of node features (globals written directly)
// ---------------------------------------------------------------------------
__global__ void split_nf_kernel(const float4* __restrict__ in, int n4)
{
    int id = blockIdx.x * blockDim.x + threadIdx.x;
    if (id >= n4) return;
    float4 v = in[id];
    __nv_bfloat16 h0, h1, h2, h3, l0, l1, l2, l3;
    split1(v.x, h0, l0); split1(v.y, h1, l1);
    split1(v.z, h2, l2); split1(v.w, h3, l3);
    uint32_t ph0 = (uint32_t)__bfloat16_as_ushort(h0) | ((uint32_t)__bfloat16_as_ushort(h1) << 16);
    uint32_t ph1 = (uint32_t)__bfloat16_as_ushort(h2) | ((uint32_t)__bfloat16_as_ushort(h3) << 16);
    uint32_t pl0 = (uint32_t)__bfloat16_as_ushort(l0) | ((uint32_t)__bfloat16_as_ushort(l1) << 16);
    uint32_t pl1 = (uint32_t)__bfloat16_as_ushort(l2) | ((uint32_t)__bfloat16_as_ushort(l3) << 16);
    *reinterpret_cast<uint2*>(g_nf_hi + 4 * (size_t)id) = make_uint2(ph0, ph1);
    *reinterpret_cast<uint2*>(g_nf_lo + 4 * (size_t)id) = make_uint2(pl0, pl1);
}

// W [K][N] fp32 row-major -> WT hi/lo [N][K] bf16. WHICH=1 -> W1 (K=2048),
// WHICH=2 -> W2 (K=1024). Globals written directly in device code.
template<int WHICH>
__global__ void transpose_split_kernel(const float* __restrict__ W)
{
    constexpr int K = (WHICH == 1) ? 2 * DNODE : DHID;
    constexpr int KSHIFT = (WHICH == 1) ? 11 : 10;
    __nv_bfloat16* hi = (WHICH == 1) ? g_W1T_hi : g_W2T_hi;
    __nv_bfloat16* lo = (WHICH == 1) ? g_W1T_lo : g_W2T_lo;
    size_t id = (size_t)blockIdx.x * blockDim.x + threadIdx.x;
    if (id >= (size_t)K * DHID) return;
    int k = (int)(id & (size_t)(K - 1));
    int n = (int)(id >> KSHIFT);
    float x = W[(size_t)k * DHID + n];
    __nv_bfloat16 h, l;
    split1(x, h, l);
    hi[id] = h;
    lo[id] = l;
}

// ---------------------------------------------------------------------------
// Split-bf16 WMMA GEMM. BM=128, BN=64, BK=32; 8 warps = 4(m) x 2(n),
// warp tile 32x32 = 2x2 wmma 16x16x16 fragments. Static smem (~32KB).
//   STAGE1: A = gather(nf hi/lo via src/dst), K=2048 -> H (bias+relu, re-split)
//   STAGE2: A = H hi/lo, K=1024 -> out fp32 (bias)
// ---------------------------------------------------------------------------
static constexpr int LDT = 40;   // smem tile leading dim (bf16 elems), 80B rows

struct __align__(16) SmemLayout {
    int   s_src[128];
    int   s_dst[128];
    float s_bias[64];
    __align__(16) __nv_bfloat16 Ah[128 * LDT];
    __align__(16) __nv_bfloat16 Al[128 * LDT];
    __align__(16) __nv_bfloat16 Bh[64 * LDT];
    __align__(16) __nv_bfloat16 Bl[64 * LDT];
};
// 1280 + (128+128+64+64)*40*2 = 32000 bytes  (< 48K static limit)

template<int KTOT, bool STAGE1>
__global__ __launch_bounds__(256)
void gemm_kernel(const int* __restrict__ src, const int* __restrict__ dst,
                 const float* __restrict__ bias, float* __restrict__ out)
{
    __shared__ SmemLayout sm;

    const int tid  = threadIdx.x;
    const int lane = tid & 31;
    const int wid  = tid >> 5;
    const int wm   = wid & 3;     // 4 warps along M (32 rows each)
    const int wn   = wid >> 2;    // 2 warps along N (32 cols each)
    const int m0 = blockIdx.y * 128;
    const int n0 = blockIdx.x * 64;

    if (STAGE1 && tid < 128) {
        sm.s_src[tid] = src[m0 + tid];
        sm.s_dst[tid] = dst[m0 + tid];
    }
    if (tid < 64) sm.s_bias[tid] = bias[n0 + tid];
    __syncthreads();

    const __nv_bfloat16* Ahi = STAGE1 ? g_nf_hi : g_H_hi;
    const __nv_bfloat16* Alo = STAGE1 ? g_nf_lo : g_H_lo;
    const __nv_bfloat16* Bhi = STAGE1 ? g_W1T_hi : g_W2T_hi;
    const __nv_bfloat16* Blo = STAGE1 ? g_W1T_lo : g_W2T_lo;

    constexpr int NT = KTOT / 32;

    wmma::fragment<wmma::accumulator, 16, 16, 16, float> acc[2][2];
    #pragma unroll
    for (int i = 0; i < 2; ++i)
        #pragma unroll
        for (int j = 0; j < 2; ++j)
            wmma::fill_fragment(acc[i][j], 0.0f);

    uint4 ra_h[2], ra_l[2], rb_h, rb_l;

    auto ldg_tile = [&](int kt) {
        const int kglob = kt * 32;
        // A: 128 rows x 32 k, 2 x uint4 per thread
        #pragma unroll
        for (int it = 0; it < 2; ++it) {
            const int u = tid + it * 256;
            const int row = u >> 2, ch = u & 3;
            size_t gA;
            if (STAGE1) {
                const int* sidx = (kglob < DNODE) ? sm.s_src : sm.s_dst;
                gA = ((size_t)sidx[row] << 10) + (kglob & (DNODE - 1)) + (ch << 3);
            } else {
                gA = ((size_t)(m0 + row) << 10) + kglob + (ch << 3);
            }
            ra_h[it] = *reinterpret_cast<const uint4*>(Ahi + gA);
            ra_l[it] = *reinterpret_cast<const uint4*>(Alo + gA);
        }
        // B: 64 rows x 32 k, 1 x uint4 per thread
        {
            const int row = tid >> 2, ch = tid & 3;
            const size_t gB = (size_t)(n0 + row) * KTOT + kglob + (ch << 3);
            rb_h = *reinterpret_cast<const uint4*>(Bhi + gB);
            rb_l = *reinterpret_cast<const uint4*>(Blo + gB);
        }
    };

    auto sts_tile = [&]() {
        #pragma unroll
        for (int it = 0; it < 2; ++it) {
            const int u = tid + it * 256;
            const int row = u >> 2, ch = u & 3;
            *reinterpret_cast<uint4*>(&sm.Ah[row * LDT + ch * 8]) = ra_h[it];
            *reinterpret_cast<uint4*>(&sm.Al[row * LDT + ch * 8]) = ra_l[it];
        }
        {
            const int row = tid >> 2, ch = tid & 3;
            *reinterpret_cast<uint4*>(&sm.Bh[row * LDT + ch * 8]) = rb_h;
            *reinterpret_cast<uint4*>(&sm.Bl[row * LDT + ch * 8]) = rb_l;
        }
    };

    auto compute = [&]() {
        #pragma unroll
        for (int kk = 0; kk < 2; ++kk) {
            wmma::fragment<wmma::matrix_a, 16, 16, 16, __nv_bfloat16, wmma::row_major> ah[2], al[2];
            wmma::fragment<wmma::matrix_b, 16, 16, 16, __nv_bfloat16, wmma::col_major> bh[2], bl[2];
            #pragma unroll
            for (int mi = 0; mi < 2; ++mi) {
                const __nv_bfloat16* pa = &sm.Ah[(wm * 32 + mi * 16) * LDT + kk * 16];
                const __nv_bfloat16* pl = &sm.Al[(wm * 32 + mi * 16) * LDT + kk * 16];
                wmma::load_matrix_sync(ah[mi], pa, LDT);
                wmma::load_matrix_sync(al[mi], pl, LDT);
            }
            #pragma unroll
            for (int nj = 0; nj < 2; ++nj) {
                const __nv_bfloat16* pb = &sm.Bh[(wn * 32 + nj * 16) * LDT + kk * 16];
                const __nv_bfloat16* pl = &sm.Bl[(wn * 32 + nj * 16) * LDT + kk * 16];
                wmma::load_matrix_sync(bh[nj], pb, LDT);
                wmma::load_matrix_sync(bl[nj], pl, LDT);
            }
            #pragma unroll
            for (int mi = 0; mi < 2; ++mi)
                #pragma unroll
                for (int nj = 0; nj < 2; ++nj) {
                    wmma::mma_sync(acc[mi][nj], ah[mi], bh[nj], acc[mi][nj]);
                    wmma::mma_sync(acc[mi][nj], ah[mi], bl[nj], acc[mi][nj]);
                    wmma::mma_sync(acc[mi][nj], al[mi], bh[nj], acc[mi][nj]);
                }
        }
    };

    ldg_tile(0);
    for (int kt = 0; kt < NT; ++kt) {
        __syncthreads();
        sts_tile();
        __syncthreads();
        if (kt + 1 < NT) ldg_tile(kt + 1);   // prefetch overlaps compute
        compute();
    }
    __syncthreads();   // tiles smem about to be reused as epilogue staging

    // ---- epilogue via store_matrix_sync staging (no fragment-layout assumptions)
    float* stage = reinterpret_cast<float*>(sm.Ah) + wid * 256;  // 1KB per warp
    const int lr = lane >> 1;          // 0..15
    const int lc = (lane & 1) * 8;     // 0 or 8

    #pragma unroll
    for (int mi = 0; mi < 2; ++mi) {
        #pragma unroll
        for (int nj = 0; nj < 2; ++nj) {
            wmma::store_matrix_sync(stage, acc[mi][nj], 16, wmma::mem_row_major);
            __syncwarp();
            const int r  = m0 + wm * 32 + mi * 16 + lr;
            const int cL = wn * 32 + nj * 16 + lc;      // local col in [0,64)
            float v[8];
            #pragma unroll
            for (int j = 0; j < 8; ++j)
                v[j] = stage[lr * 16 + lc + j] + sm.s_bias[cL + j];

            const size_t o = ((size_t)r << 10) + n0 + cL;
            if (STAGE1) {
                uint32_t ph[4], pl[4];
                #pragma unroll
                for (int j = 0; j < 8; j += 2) {
                    float v0 = v[j] > 0.0f ? v[j] : 0.0f;
                    float v1 = v[j + 1] > 0.0f ? v[j + 1] : 0.0f;
                    __nv_bfloat16 h0, h1, l0, l1;
                    split1(v0, h0, l0);
                    split1(v1, h1, l1);
                    ph[j >> 1] = (uint32_t)__bfloat16_as_ushort(h0) |
                                 ((uint32_t)__bfloat16_as_ushort(h1) << 16);
                    pl[j >> 1] = (uint32_t)__bfloat16_as_ushort(l0) |
                                 ((uint32_t)__bfloat16_as_ushort(l1) << 16);
                }
                *reinterpret_cast<uint4*>(g_H_hi + o) = make_uint4(ph[0], ph[1], ph[2], ph[3]);
                *reinterpret_cast<uint4*>(g_H_lo + o) = make_uint4(pl[0], pl[1], pl[2], pl[3]);
            } else {
                float4* d4 = reinterpret_cast<float4*>(out + o);
                d4[0] = make_float4(v[0], v[1], v[2], v[3]);
                d4[1] = make_float4(v[4], v[5], v[6], v[7]);
            }
            __syncwarp();
        }
    }
}

// ---------------------------------------------------------------------------
extern "C" void kernel_launch(void* const* d_in, const int* in_sizes, int n_in,
                              void* d_out, int out_size)
{
    const float* nf  = (const float*)d_in[0];
    const int*   src = (const int*)d_in[1];   // JAX int64 downcasts to int32 (x64 off)
    const int*   dst = (const int*)d_in[2];
    const float* W1  = (const float*)d_in[3];
    const float* b1  = (const float*)d_in[4];
    const float* W2  = (const float*)d_in[5];
    const float* b2  = (const float*)d_in[6];
    float*       out = (float*)d_out;

    // 1) split node features into bf16 hi/lo (globals written device-side)
    {
        int n4 = (NNODES * DNODE) / 4;
        split_nf_kernel<<<(n4 + 255) / 256, 256>>>((const float4*)nf, n4);
    }
    // 2) transpose+split weights
    {
        size_t t1 = (size_t)(2 * DNODE) * DHID;
        transpose_split_kernel<1><<<(unsigned)((t1 + 255) / 256), 256>>>(W1);
        size_t t2 = (size_t)DHID * DHID;
        transpose_split_kernel<2><<<(unsigned)((t2 + 255) / 256), 256>>>(W2);
    }
    // 3) stage 1: H = relu(concat @ W1 + b1)  (K = 2048)
    {
        dim3 grid(DHID / 64, NEDGES / 128);
        gemm_kernel<2 * DNODE, true><<<grid, 256>>>(src, dst, b1, nullptr);
    }
    // 4) stage 2: out = H @ W2 + b2  (K = 1024)
    {
        dim3 grid(DHID / 64, NEDGES / 128);
        gemm_kernel<DHID, false><<<grid, 256>>>(src, dst, b2, out);
    }
}

// round 8
// speedup vs baseline: 1.8511x; 1.0744x over previous
#include <cuda_runtime.h>
#include <cuda_bf16.h>
#include <mma.h>
#include <cstdint>

using namespace nvcuda;

#define NEDGES 65536
#define NNODES 50000
#define DNODE  1024
#define DHID   1024

// ---------------------------------------------------------------------------
// Device scratch (static). Referenced ONLY from device code — passing a
// __device__ array as a kernel argument from host passes the host shadow
// address (GB300/ATS silently writes host memory!).
// ---------------------------------------------------------------------------
__device__ __nv_bfloat16 g_nf_hi[(size_t)NNODES * DNODE];
__device__ __nv_bfloat16 g_nf_lo[(size_t)NNODES * DNODE];
__device__ __nv_bfloat16 g_W1T_hi[(size_t)DHID * (2 * DNODE)];   // [N=1024][K=2048]
__device__ __nv_bfloat16 g_W1T_lo[(size_t)DHID * (2 * DNODE)];
__device__ __nv_bfloat16 g_W2T_hi[(size_t)DHID * DHID];          // [N=1024][K=1024]
__device__ __nv_bfloat16 g_W2T_lo[(size_t)DHID * DHID];
__device__ __nv_bfloat16 g_H_hi[(size_t)NEDGES * DHID];
__device__ __nv_bfloat16 g_H_lo[(size_t)NEDGES * DHID];

__device__ __forceinline__ void split1(float x, __nv_bfloat16& h, __nv_bfloat16& l) {
    h = __float2bfloat16(x);
    l = __float2bfloat16(x - __bfloat162float(h));
}

__device__ __forceinline__ uint32_t smem_u32(const void* p) {
    uint32_t a;
    asm("{ .reg .u64 t; cvta.to.shared.u64 t, %1; cvt.u32.u64 %0, t; }" : "=r"(a) : "l"(p));
    return a;
}
__device__ __forceinline__ void cp16(uint32_t saddr, const void* g) {
    asm volatile("cp.async.cg.shared.global [%0], [%1], 16;" :: "r"(saddr), "l"(g));
}
__device__ __forceinline__ void cp_commit() {
    asm volatile("cp.async.commit_group;");
}
template<int N>
__device__ __forceinline__ void cp_wait() {
    asm volatile("cp.async.wait_group %0;" :: "n"(N));
}

// ---------------------------------------------------------------------------
// Pre-pass kernels (globals written device-side)
// ---------------------------------------------------------------------------
__global__ void split_nf_kernel(const float4* __restrict__ in, int n4)
{
    int id = blockIdx.x * blockDim.x + threadIdx.x;
    if (id >= n4) return;
    float4 v = in[id];
    __nv_bfloat16 h0, h1, h2, h3, l0, l1, l2, l3;
    split1(v.x, h0, l0); split1(v.y, h1, l1);
    split1(v.z, h2, l2); split1(v.w, h3, l3);
    uint32_t ph0 = (uint32_t)__bfloat16_as_ushort(h0) | ((uint32_t)__bfloat16_as_ushort(h1) << 16);
    uint32_t ph1 = (uint32_t)__bfloat16_as_ushort(h2) | ((uint32_t)__bfloat16_as_ushort(h3) << 16);
    uint32_t pl0 = (uint32_t)__bfloat16_as_ushort(l0) | ((uint32_t)__bfloat16_as_ushort(l1) << 16);
    uint32_t pl1 = (uint32_t)__bfloat16_as_ushort(l2) | ((uint32_t)__bfloat16_as_ushort(l3) << 16);
    *reinterpret_cast<uint2*>(g_nf_hi + 4 * (size_t)id) = make_uint2(ph0, ph1);
    *reinterpret_cast<uint2*>(g_nf_lo + 4 * (size_t)id) = make_uint2(pl0, pl1);
}

template<int WHICH>
__global__ void transpose_split_kernel(const float* __restrict__ W)
{
    constexpr int K = (WHICH == 1) ? 2 * DNODE : DHID;
    constexpr int KSHIFT = (WHICH == 1) ? 11 : 10;
    __nv_bfloat16* hi = (WHICH == 1) ? g_W1T_hi : g_W2T_hi;
    __nv_bfloat16* lo = (WHICH == 1) ? g_W1T_lo : g_W2T_lo;
    size_t id = (size_t)blockIdx.x * blockDim.x + threadIdx.x;
    if (id >= (size_t)K * DHID) return;
    int k = (int)(id & (size_t)(K - 1));
    int n = (int)(id >> KSHIFT);
    float x = W[(size_t)k * DHID + n];
    __nv_bfloat16 h, l;
    split1(x, h, l);
    hi[id] = h;
    lo[id] = l;
}

// ---------------------------------------------------------------------------
// Split-bf16 WMMA GEMM v2.
//   BM=128, BN=128, BK=32; 4 warps (2m x 2n), warp tile 64x64 (4x4 frags).
//   cp.async double-buffered pipeline, dynamic smem (~83KB), 2 CTAs/SM.
//   STAGE1: A = gather(nf hi/lo via src/dst), K=2048 -> H (bias+relu, re-split)
//   STAGE2: A = H hi/lo, K=1024 -> out fp32 (bias)
// ---------------------------------------------------------------------------
static constexpr int LDT  = 40;                 // bf16 elems per smem row (80B)
static constexpr int MBUF = 128 * LDT * 2;      // 10240 B: one matrix buffer
static constexpr int SBUF = 4 * MBUF;           // 40960 B: Ah|Al|Bh|Bl
static constexpr int HDR  = 1536;               // s_src 512 | s_dst 512 | s_bias 512
static constexpr int SMEM_BYTES = HDR + 2 * SBUF;   // 83456

template<int KTOT, bool STAGE1>
__global__ __launch_bounds__(128)
void gemm_kernel(const int* __restrict__ src, const int* __restrict__ dst,
                 const float* __restrict__ bias, float* __restrict__ out)
{
    extern __shared__ char smem[];
    int*   s_src  = (int*)smem;
    int*   s_dst  = (int*)(smem + 512);
    float* s_bias = (float*)(smem + 1024);
    char*  tiles  = smem + HDR;
    const uint32_t tiles_u32 = smem_u32(tiles);

    const int tid  = threadIdx.x;
    const int lane = tid & 31;
    const int wid  = tid >> 5;
    const int wm   = wid & 1;      // 2 warps along M (64 rows each)
    const int wn   = wid >> 1;     // 2 warps along N (64 cols each)
    const int m0 = blockIdx.y * 128;
    const int n0 = blockIdx.x * 128;

    if (STAGE1) {
        s_src[tid] = src[m0 + tid];
        s_dst[tid] = dst[m0 + tid];
    }
    s_bias[tid] = bias[n0 + tid];
    __syncthreads();

    const __nv_bfloat16* Ahi = STAGE1 ? g_nf_hi : g_H_hi;
    const __nv_bfloat16* Alo = STAGE1 ? g_nf_lo : g_H_lo;
    const __nv_bfloat16* Bhi = STAGE1 ? g_W1T_hi : g_W2T_hi;
    const __nv_bfloat16* Blo = STAGE1 ? g_W1T_lo : g_W2T_lo;

    constexpr int NT = KTOT / 32;

    wmma::fragment<wmma::accumulator, 16, 16, 16, float> acc[4][4];
    #pragma unroll
    for (int i = 0; i < 4; ++i)
        #pragma unroll
        for (int j = 0; j < 4; ++j)
            wmma::fill_fragment(acc[i][j], 0.0f);

    // cp.async one k-tile into stage buffer s. Thread t handles row t of both
    // A (128x32) and B (128x32), 4 x 16B chunks each, hi+lo.
    auto issue_tile = [&](int kt, int s) {
        const int kglob = kt * 32;
        const int row = tid;
        const uint32_t base = tiles_u32 + s * SBUF + row * (LDT * 2);
        size_t gA;
        if (STAGE1) {
            const int* sidx = (kglob < DNODE) ? s_src : s_dst;
            gA = ((size_t)sidx[row] << 10) + (kglob & (DNODE - 1));
        } else {
            gA = ((size_t)(m0 + row) << 10) + kglob;
        }
        const size_t gB = (size_t)(n0 + row) * KTOT + kglob;
        #pragma unroll
        for (int ch = 0; ch < 4; ++ch) {
            cp16(base + 0 * MBUF + ch * 16, Ahi + gA + ch * 8);
            cp16(base + 1 * MBUF + ch * 16, Alo + gA + ch * 8);
            cp16(base + 2 * MBUF + ch * 16, Bhi + gB + ch * 8);
            cp16(base + 3 * MBUF + ch * 16, Blo + gB + ch * 8);
        }
    };

    auto compute = [&](int s) {
        const __nv_bfloat16* Ah = (const __nv_bfloat16*)(tiles + s * SBUF + 0 * MBUF);
        const __nv_bfloat16* Al = (const __nv_bfloat16*)(tiles + s * SBUF + 1 * MBUF);
        const __nv_bfloat16* Bh = (const __nv_bfloat16*)(tiles + s * SBUF + 2 * MBUF);
        const __nv_bfloat16* Bl = (const __nv_bfloat16*)(tiles + s * SBUF + 3 * MBUF);
        #pragma unroll
        for (int kk = 0; kk < 2; ++kk) {
            wmma::fragment<wmma::matrix_a, 16, 16, 16, __nv_bfloat16, wmma::row_major> ah[4], al[4];
            #pragma unroll
            for (int mi = 0; mi < 4; ++mi) {
                const int r = wm * 64 + mi * 16;
                wmma::load_matrix_sync(ah[mi], Ah + r * LDT + kk * 16, LDT);
                wmma::load_matrix_sync(al[mi], Al + r * LDT + kk * 16, LDT);
            }
            #pragma unroll
            for (int nj = 0; nj < 4; ++nj) {
                wmma::fragment<wmma::matrix_b, 16, 16, 16, __nv_bfloat16, wmma::col_major> bh, bl;
                const int r = wn * 64 + nj * 16;
                wmma::load_matrix_sync(bh, Bh + r * LDT + kk * 16, LDT);
                wmma::load_matrix_sync(bl, Bl + r * LDT + kk * 16, LDT);
                #pragma unroll
                for (int mi = 0; mi < 4; ++mi) {
                    wmma::mma_sync(acc[mi][nj], ah[mi], bh, acc[mi][nj]);
                    wmma::mma_sync(acc[mi][nj], ah[mi], bl, acc[mi][nj]);
                    wmma::mma_sync(acc[mi][nj], al[mi], bh, acc[mi][nj]);
                }
            }
        }
    };

    issue_tile(0, 0);
    cp_commit();
    for (int kt = 0; kt < NT; ++kt) {
        if (kt + 1 < NT) {
            issue_tile(kt + 1, (kt + 1) & 1);
            cp_commit();
            cp_wait<1>();
        } else {
            cp_wait<0>();
        }
        __syncthreads();
        compute(kt & 1);
        __syncthreads();   // compute done before buffer reuse by cp.async
    }

    // ---- epilogue via store_matrix_sync staging (layout-assumption-free) ----
    float* stage = reinterpret_cast<float*>(tiles) + wid * 256;  // 1KB per warp
    const int lr = lane >> 1;
    const int lc = (lane & 1) * 8;

    #pragma unroll
    for (int mi = 0; mi < 4; ++mi) {
        #pragma unroll
        for (int nj = 0; nj < 4; ++nj) {
            wmma::store_matrix_sync(stage, acc[mi][nj], 16, wmma::mem_row_major);
            __syncwarp();
            const int r  = m0 + wm * 64 + mi * 16 + lr;
            const int cL = wn * 64 + nj * 16 + lc;
            float v[8];
            #pragma unroll
            for (int j = 0; j < 8; ++j)
                v[j] = stage[lr * 16 + lc + j] + s_bias[cL + j];

            const size_t o = ((size_t)r << 10) + n0 + cL;
            if (STAGE1) {
                uint32_t ph[4], pl[4];
                #pragma unroll
                for (int j = 0; j < 8; j += 2) {
                    float v0 = v[j] > 0.0f ? v[j] : 0.0f;
                    float v1 = v[j + 1] > 0.0f ? v[j + 1] : 0.0f;
                    __nv_bfloat16 h0, h1, l0, l1;
                    split1(v0, h0, l0);
                    split1(v1, h1, l1);
                    ph[j >> 1] = (uint32_t)__bfloat16_as_ushort(h0) |
                                 ((uint32_t)__bfloat16_as_ushort(h1) << 16);
                    pl[j >> 1] = (uint32_t)__bfloat16_as_ushort(l0) |
                                 ((uint32_t)__bfloat16_as_ushort(l1) << 16);
                }
                *reinterpret_cast<uint4*>(g_H_hi + o) = make_uint4(ph[0], ph[1], ph[2], ph[3]);
                *reinterpret_cast<uint4*>(g_H_lo + o) = make_uint4(pl[0], pl[1], pl[2], pl[3]);
            } else {
                float4* d4 = reinterpret_cast<float4*>(out + o);
                d4[0] = make_float4(v[0], v[1], v[2], v[3]);
                d4[1] = make_float4(v[4], v[5], v[6], v[7]);
            }
            __syncwarp();
        }
    }
}

// ---------------------------------------------------------------------------
extern "C" void kernel_launch(void* const* d_in, const int* in_sizes, int n_in,
                              void* d_out, int out_size)
{
    const float* nf  = (const float*)d_in[0];
    const int*   src = (const int*)d_in[1];   // JAX int64 downcasts to int32 (x64 off)
    const int*   dst = (const int*)d_in[2];
    const float* W1  = (const float*)d_in[3];
    const float* b1  = (const float*)d_in[4];
    const float* W2  = (const float*)d_in[5];
    const float* b2  = (const float*)d_in[6];
    float*       out = (float*)d_out;

    cudaFuncSetAttribute(gemm_kernel<2 * DNODE, true>,
                         cudaFuncAttributeMaxDynamicSharedMemorySize, SMEM_BYTES);
    cudaFuncSetAttribute(gemm_kernel<DHID, false>,
                         cudaFuncAttributeMaxDynamicSharedMemorySize, SMEM_BYTES);

    // 1) split node features into bf16 hi/lo
    {
        int n4 = (NNODES * DNODE) / 4;
        split_nf_kernel<<<(n4 + 255) / 256, 256>>>((const float4*)nf, n4);
    }
    // 2) transpose+split weights
    {
        size_t t1 = (size_t)(2 * DNODE) * DHID;
        transpose_split_kernel<1><<<(unsigned)((t1 + 255) / 256), 256>>>(W1);
        size_t t2 = (size_t)DHID * DHID;
        transpose_split_kernel<2><<<(unsigned)((t2 + 255) / 256), 256>>>(W2);
    }
    // 3) stage 1: H = relu(concat @ W1 + b1)  (K = 2048)
    {
        dim3 grid(DHID / 128, NEDGES / 128);
        gemm_kernel<2 * DNODE, true><<<grid, 128, SMEM_BYTES>>>(src, dst, b1, nullptr);
    }
    // 4) stage 2: out = H @ W2 + b2  (K = 1024)
    {
        dim3 grid(DHID / 128, NEDGES / 128);
        gemm_kernel<DHID, false><<<grid, 128, SMEM_BYTES>>>(src, dst, b2, out);
    }
}

// round 9
// speedup vs baseline: 2.2166x; 1.1975x over previous
#include <cuda_runtime.h>
#include <cuda_bf16.h>
#include <mma.h>
#include <cstdint>

using namespace nvcuda;

#define NEDGES 65536
#define NNODES 50000
#define DNODE  1024
#define DHID   1024

// ---------------------------------------------------------------------------
// Device scratch (static). Referenced ONLY from device code — passing a
// __device__ array as a kernel argument from host passes the host shadow
// address (GB300/ATS silently writes host memory!).
// ---------------------------------------------------------------------------
__device__ __nv_bfloat16 g_nf_hi[(size_t)NNODES * DNODE];
__device__ __nv_bfloat16 g_nf_lo[(size_t)NNODES * DNODE];
__device__ __nv_bfloat16 g_W1T_hi[(size_t)DHID * (2 * DNODE)];   // [N=1024][K=2048]
__device__ __nv_bfloat16 g_W1T_lo[(size_t)DHID * (2 * DNODE)];
__device__ __nv_bfloat16 g_W2T_hi[(size_t)DHID * DHID];          // [N=1024][K=1024]
__device__ __nv_bfloat16 g_W2T_lo[(size_t)DHID * DHID];
__device__ __nv_bfloat16 g_H_hi[(size_t)NEDGES * DHID];
__device__ __nv_bfloat16 g_H_lo[(size_t)NEDGES * DHID];

__device__ __forceinline__ void split1(float x, __nv_bfloat16& h, __nv_bfloat16& l) {
    h = __float2bfloat16(x);
    l = __float2bfloat16(x - __bfloat162float(h));
}

__device__ __forceinline__ uint32_t smem_u32(const void* p) {
    uint32_t a;
    asm("{ .reg .u64 t; cvta.to.shared.u64 t, %1; cvt.u32.u64 %0, t; }" : "=r"(a) : "l"(p));
    return a;
}
__device__ __forceinline__ void cp16(uint32_t saddr, const void* g) {
    asm volatile("cp.async.cg.shared.global [%0], [%1], 16;" :: "r"(saddr), "l"(g));
}
__device__ __forceinline__ void cp_commit() {
    asm volatile("cp.async.commit_group;");
}
template<int N>
__device__ __forceinline__ void cp_wait() {
    asm volatile("cp.async.wait_group %0;" :: "n"(N));
}

// ---------------------------------------------------------------------------
// Pre-pass kernels (globals written device-side)
// ---------------------------------------------------------------------------
__global__ void split_nf_kernel(const float4* __restrict__ in, int n4)
{
    int id = blockIdx.x * blockDim.x + threadIdx.x;
    if (id >= n4) return;
    float4 v = in[id];
    __nv_bfloat16 h0, h1, h2, h3, l0, l1, l2, l3;
    split1(v.x, h0, l0); split1(v.y, h1, l1);
    split1(v.z, h2, l2); split1(v.w, h3, l3);
    uint32_t ph0 = (uint32_t)__bfloat16_as_ushort(h0) | ((uint32_t)__bfloat16_as_ushort(h1) << 16);
    uint32_t ph1 = (uint32_t)__bfloat16_as_ushort(h2) | ((uint32_t)__bfloat16_as_ushort(h3) << 16);
    uint32_t pl0 = (uint32_t)__bfloat16_as_ushort(l0) | ((uint32_t)__bfloat16_as_ushort(l1) << 16);
    uint32_t pl1 = (uint32_t)__bfloat16_as_ushort(l2) | ((uint32_t)__bfloat16_as_ushort(l3) << 16);
    *reinterpret_cast<uint2*>(g_nf_hi + 4 * (size_t)id) = make_uint2(ph0, ph1);
    *reinterpret_cast<uint2*>(g_nf_lo + 4 * (size_t)id) = make_uint2(pl0, pl1);
}

template<int WHICH>
__global__ void transpose_split_kernel(const float* __restrict__ W)
{
    constexpr int K = (WHICH == 1) ? 2 * DNODE : DHID;
    constexpr int KSHIFT = (WHICH == 1) ? 11 : 10;
    __nv_bfloat16* hi = (WHICH == 1) ? g_W1T_hi : g_W2T_hi;
    __nv_bfloat16* lo = (WHICH == 1) ? g_W1T_lo : g_W2T_lo;
    size_t id = (size_t)blockIdx.x * blockDim.x + threadIdx.x;
    if (id >= (size_t)K * DHID) return;
    int k = (int)(id & (size_t)(K - 1));
    int n = (int)(id >> KSHIFT);
    float x = W[(size_t)k * DHID + n];
    __nv_bfloat16 h, l;
    split1(x, h, l);
    hi[id] = h;
    lo[id] = l;
}

// ---------------------------------------------------------------------------
// Split-bf16 WMMA GEMM v3.
//   BM=128, BN=128, BK=32; 8 warps (4m x 2n), warp tile 32x64 (2x4 frags).
//   cp.async double-buffered, dynamic smem (~83KB), 2 CTAs/SM (16 warps/SM).
//   STAGE1: A = gather(nf hi/lo via src/dst), K=2048 -> H (bias+relu, re-split)
//   STAGE2: A = H hi/lo, K=1024 -> out fp32 (bias)
// ---------------------------------------------------------------------------
static constexpr int LDT  = 40;                 // bf16 elems per smem row (80B)
static constexpr int MBUF = 128 * LDT * 2;      // 10240 B: one matrix buffer
static constexpr int SBUF = 4 * MBUF;           // 40960 B: Ah|Al|Bh|Bl
static constexpr int HDR  = 1536;               // s_src 512 | s_dst 512 | s_bias 512
static constexpr int SMEM_BYTES = HDR + 2 * SBUF;   // 83456

template<int KTOT, bool STAGE1>
__global__ __launch_bounds__(256, 2)
void gemm_kernel(const int* __restrict__ src, const int* __restrict__ dst,
                 const float* __restrict__ bias, float* __restrict__ out)
{
    extern __shared__ char smem[];
    int*   s_src  = (int*)smem;
    int*   s_dst  = (int*)(smem + 512);
    float* s_bias = (float*)(smem + 1024);
    char*  tiles  = smem + HDR;
    const uint32_t tiles_u32 = smem_u32(tiles);

    const int tid  = threadIdx.x;
    const int lane = tid & 31;
    const int wid  = tid >> 5;
    const int wm   = wid & 3;      // 4 warps along M (32 rows each)
    const int wn   = wid >> 2;     // 2 warps along N (64 cols each)
    const int m0 = blockIdx.y * 128;
    const int n0 = blockIdx.x * 128;

    if (tid < 128) {
        if (STAGE1) {
            s_src[tid] = src[m0 + tid];
            s_dst[tid] = dst[m0 + tid];
        }
        s_bias[tid] = bias[n0 + tid];
    }
    __syncthreads();

    const __nv_bfloat16* Ahi = STAGE1 ? g_nf_hi : g_H_hi;
    const __nv_bfloat16* Alo = STAGE1 ? g_nf_lo : g_H_lo;
    const __nv_bfloat16* Bhi = STAGE1 ? g_W1T_hi : g_W2T_hi;
    const __nv_bfloat16* Blo = STAGE1 ? g_W1T_lo : g_W2T_lo;

    constexpr int NT = KTOT / 32;

    wmma::fragment<wmma::accumulator, 16, 16, 16, float> acc[2][4];
    #pragma unroll
    for (int i = 0; i < 2; ++i)
        #pragma unroll
        for (int j = 0; j < 4; ++j)
            wmma::fill_fragment(acc[i][j], 0.0f);

    // cp.async one k-tile into stage s. 256 threads: thread t -> row t/2,
    // 32B half (t&1) of the 64B row, for Ah/Al/Bh/Bl (8 x 16B chunks).
    auto issue_tile = [&](int kt, int s) {
        const int kglob = kt * 32;
        const int row  = tid >> 1;
        const int half = (tid & 1) * 16;   // bf16 elem offset within the 32-elem row
        const uint32_t base = tiles_u32 + s * SBUF + row * (LDT * 2) + half * 2;
        size_t gA;
        if (STAGE1) {
            const int* sidx = (kglob < DNODE) ? s_src : s_dst;
            gA = ((size_t)sidx[row] << 10) + (kglob & (DNODE - 1)) + half;
        } else {
            gA = ((size_t)(m0 + row) << 10) + kglob + half;
        }
        const size_t gB = (size_t)(n0 + row) * KTOT + kglob + half;
        #pragma unroll
        for (int ch = 0; ch < 2; ++ch) {
            cp16(base + 0 * MBUF + ch * 16, Ahi + gA + ch * 8);
            cp16(base + 1 * MBUF + ch * 16, Alo + gA + ch * 8);
            cp16(base + 2 * MBUF + ch * 16, Bhi + gB + ch * 8);
            cp16(base + 3 * MBUF + ch * 16, Blo + gB + ch * 8);
        }
    };

    auto compute = [&](int s) {
        const __nv_bfloat16* Ah = (const __nv_bfloat16*)(tiles + s * SBUF + 0 * MBUF);
        const __nv_bfloat16* Al = (const __nv_bfloat16*)(tiles + s * SBUF + 1 * MBUF);
        const __nv_bfloat16* Bh = (const __nv_bfloat16*)(tiles + s * SBUF + 2 * MBUF);
        const __nv_bfloat16* Bl = (const __nv_bfloat16*)(tiles + s * SBUF + 3 * MBUF);
        #pragma unroll
        for (int kk = 0; kk < 2; ++kk) {
            wmma::fragment<wmma::matrix_a, 16, 16, 16, __nv_bfloat16, wmma::row_major> ah[2], al[2];
            #pragma unroll
            for (int mi = 0; mi < 2; ++mi) {
                const int r = wm * 32 + mi * 16;
                wmma::load_matrix_sync(ah[mi], Ah + r * LDT + kk * 16, LDT);
                wmma::load_matrix_sync(al[mi], Al + r * LDT + kk * 16, LDT);
            }
            #pragma unroll
            for (int nj = 0; nj < 4; ++nj) {
                wmma::fragment<wmma::matrix_b, 16, 16, 16, __nv_bfloat16, wmma::col_major> bh, bl;
                const int r = wn * 64 + nj * 16;
                wmma::load_matrix_sync(bh, Bh + r * LDT + kk * 16, LDT);
                wmma::load_matrix_sync(bl, Bl + r * LDT + kk * 16, LDT);
                #pragma unroll
                for (int mi = 0; mi < 2; ++mi) {
                    wmma::mma_sync(acc[mi][nj], ah[mi], bh, acc[mi][nj]);
                    wmma::mma_sync(acc[mi][nj], ah[mi], bl, acc[mi][nj]);
                    wmma::mma_sync(acc[mi][nj], al[mi], bh, acc[mi][nj]);
                }
            }
        }
    };

    issue_tile(0, 0);
    cp_commit();
    for (int kt = 0; kt < NT; ++kt) {
        if (kt + 1 < NT) {
            issue_tile(kt + 1, (kt + 1) & 1);
            cp_commit();
            cp_wait<1>();
        } else {
            cp_wait<0>();
        }
        __syncthreads();
        compute(kt & 1);
        __syncthreads();   // compute done before buffer reuse by cp.async
    }

    // ---- epilogue via store_matrix_sync staging (layout-assumption-free) ----
    float* stage = reinterpret_cast<float*>(tiles) + wid * 256;  // 1KB per warp
    const int lr = lane >> 1;
    const int lc = (lane & 1) * 8;

    #pragma unroll
    for (int mi = 0; mi < 2; ++mi) {
        #pragma unroll
        for (int nj = 0; nj < 4; ++nj) {
            wmma::store_matrix_sync(stage, acc[mi][nj], 16, wmma::mem_row_major);
            __syncwarp();
            const int r  = m0 + wm * 32 + mi * 16 + lr;
            const int cL = wn * 64 + nj * 16 + lc;
            float v[8];
            #pragma unroll
            for (int j = 0; j < 8; ++j)
                v[j] = stage[lr * 16 + lc + j] + s_bias[cL + j];

            const size_t o = ((size_t)r << 10) + n0 + cL;
            if (STAGE1) {
                uint32_t ph[4], pl[4];
                #pragma unroll
                for (int j = 0; j < 8; j += 2) {
                    float v0 = v[j] > 0.0f ? v[j] : 0.0f;
                    float v1 = v[j + 1] > 0.0f ? v[j + 1] : 0.0f;
                    __nv_bfloat16 h0, h1, l0, l1;
                    split1(v0, h0, l0);
                    split1(v1, h1, l1);
                    ph[j >> 1] = (uint32_t)__bfloat16_as_ushort(h0) |
                                 ((uint32_t)__bfloat16_as_ushort(h1) << 16);
                    pl[j >> 1] = (uint32_t)__bfloat16_as_ushort(l0) |
                                 ((uint32_t)__bfloat16_as_ushort(l1) << 16);
                }
                *reinterpret_cast<uint4*>(g_H_hi + o) = make_uint4(ph[0], ph[1], ph[2], ph[3]);
                *reinterpret_cast<uint4*>(g_H_lo + o) = make_uint4(pl[0], pl[1], pl[2], pl[3]);
            } else {
                float4* d4 = reinterpret_cast<float4*>(out + o);
                d4[0] = make_float4(v[0], v[1], v[2], v[3]);
                d4[1] = make_float4(v[4], v[5], v[6], v[7]);
            }
            __syncwarp();
        }
    }
}

// ---------------------------------------------------------------------------
extern "C" void kernel_launch(void* const* d_in, const int* in_sizes, int n_in,
                              void* d_out, int out_size)
{
    const float* nf  = (const float*)d_in[0];
    const int*   src = (const int*)d_in[1];   // JAX int64 downcasts to int32 (x64 off)
    const int*   dst = (const int*)d_in[2];
    const float* W1  = (const float*)d_in[3];
    const float* b1  = (const float*)d_in[4];
    const float* W2  = (const float*)d_in[5];
    const float* b2  = (const float*)d_in[6];
    float*       out = (float*)d_out;

    cudaFuncSetAttribute(gemm_kernel<2 * DNODE, true>,
                         cudaFuncAttributeMaxDynamicSharedMemorySize, SMEM_BYTES);
    cudaFuncSetAttribute(gemm_kernel<DHID, false>,
                         cudaFuncAttributeMaxDynamicSharedMemorySize, SMEM_BYTES);

    // 1) split node features into bf16 hi/lo
    {
        int n4 = (NNODES * DNODE) / 4;
        split_nf_kernel<<<(n4 + 255) / 256, 256>>>((const float4*)nf, n4);
    }
    // 2) transpose+split weights
    {
        size_t t1 = (size_t)(2 * DNODE) * DHID;
        transpose_split_kernel<1><<<(unsigned)((t1 + 255) / 256), 256>>>(W1);
        size_t t2 = (size_t)DHID * DHID;
        transpose_split_kernel<2><<<(unsigned)((t2 + 255) / 256), 256>>>(W2);
    }
    // 3) stage 1: H = relu(concat @ W1 + b1)  (K = 2048)
    {
        dim3 grid(DHID / 128, NEDGES / 128);
        gemm_kernel<2 * DNODE, true><<<grid, 256, SMEM_BYTES>>>(src, dst, b1, nullptr);
    }
    // 4) stage 2: out = H @ W2 + b2  (K = 1024)
    {
        dim3 grid(DHID / 128, NEDGES / 128);
        gemm_kernel<DHID, false><<<grid, 256, SMEM_BYTES>>>(src, dst, b2, out);
    }
}